// round 10
// baseline (speedup 1.0000x reference)
#include <cuda_runtime.h>
#include <cuda_bf16.h>
#include <cstdint>

// Problem constants: B=2, T=2048, D=1024, H=16, dk=64
// Pre-split hi/lo bf16-pair word arrays (word = 2 bf16 = 1 fp32 slot)
__device__ uint32_t g_Xhi[2097152],  g_Xlo[2097152];    // x       (B,T,D)
__device__ uint32_t g_WQhi[1572864], g_WQlo[1572864];   // w_qkv   (3D,D)
__device__ uint32_t g_WPhi[524288],  g_WPlo[524288];    // w_proj  (D,D)
__device__ uint32_t g_Qhi[2097152],  g_Qlo[2097152];    // head-major (B,H,T,dk)
__device__ uint32_t g_Khi[2097152],  g_Klo[2097152];
__device__ uint32_t g_Vhi[2097152],  g_Vlo[2097152];
__device__ uint32_t g_Ohi[2097152],  g_Olo[2097152];

// ---------------------------------------------------------------------------
// Helpers
// ---------------------------------------------------------------------------
__device__ __forceinline__ void split2(float f0, float f1, uint32_t& hi, uint32_t& lo) {
    __nv_bfloat162 h = __floats2bfloat162_rn(f0, f1);
    float r0 = f0 - __bfloat162float(h.x);
    float r1 = f1 - __bfloat162float(h.y);
    __nv_bfloat162 l = __floats2bfloat162_rn(r0, r1);
    hi = *(uint32_t*)&h;
    lo = *(uint32_t*)&l;
}
__device__ __forceinline__ void mma_bf16(float* d, const uint32_t* a, const uint32_t* b) {
    asm volatile(
        "mma.sync.aligned.m16n8k16.row.col.f32.bf16.bf16.f32 "
        "{%0,%1,%2,%3}, {%4,%5,%6,%7}, {%8,%9}, {%0,%1,%2,%3};"
        : "+f"(d[0]), "+f"(d[1]), "+f"(d[2]), "+f"(d[3])
        : "r"(a[0]), "r"(a[1]), "r"(a[2]), "r"(a[3]), "r"(b[0]), "r"(b[1]));
}
__device__ __forceinline__ void ldm_x4(uint32_t* r, uint32_t addr) {
    asm volatile("ldmatrix.sync.aligned.m8n8.x4.shared.b16 {%0,%1,%2,%3}, [%4];"
                 : "=r"(r[0]), "=r"(r[1]), "=r"(r[2]), "=r"(r[3]) : "r"(addr));
}
__device__ __forceinline__ void ldm_x4t(uint32_t* r, uint32_t addr) {
    asm volatile("ldmatrix.sync.aligned.m8n8.x4.trans.shared.b16 {%0,%1,%2,%3}, [%4];"
                 : "=r"(r[0]), "=r"(r[1]), "=r"(r[2]), "=r"(r[3]) : "r"(addr));
}
__device__ __forceinline__ uint32_t smem_addr(const void* p) {
    return (uint32_t)__cvta_generic_to_shared(p);
}
__device__ __forceinline__ void cpa16(uint32_t saddr, const void* g) {
    asm volatile("cp.async.cg.shared.global [%0], [%1], 16;" :: "r"(saddr), "l"(g));
}
#define CP_COMMIT() asm volatile("cp.async.commit_group;" ::: "memory")
#define CP_WAIT0()  asm volatile("cp.async.wait_group 0;" ::: "memory")
#define CP_WAIT1()  asm volatile("cp.async.wait_group 1;" ::: "memory")

// ---------------------------------------------------------------------------
// Pre-split: fp32 -> hi/lo bf16-pair words. Each thread: 8 floats.
// ---------------------------------------------------------------------------
__global__ __launch_bounds__(256) void presplit_kernel(
    const float4* __restrict__ src, uint4* __restrict__ hi, uint4* __restrict__ lo)
{
    const int i = blockIdx.x * 256 + threadIdx.x;
    const float4 a = src[2 * i], b = src[2 * i + 1];
    uint4 h, l;
    split2(a.x, a.y, h.x, l.x);
    split2(a.z, a.w, h.y, l.y);
    split2(b.x, b.y, h.z, l.z);
    split2(b.z, b.w, h.w, l.w);
    hi[i] = h;
    lo[i] = l;
}

// ---------------------------------------------------------------------------
// GEMM: out[m,n] = sum_k A[m,k]*W[n,k], split-bf16 (3 mma terms).
// CTA 128x128, 8 warps (warp tile 64x32). K-chunk 64 (32 words), 16 stages,
// cp.async double-buffered; shared stride 36 words (ldmatrix conflict-free).
// MODE 0: A = pre-split x; epilogue RoPE + split-bf16 Q/K/V store (Q * 1/8).
// MODE 1: A = pre-split O (head-major); epilogue fp32 store to out.
// ---------------------------------------------------------------------------
#define GSW 36
#define GARR (128 * GSW)        // words per array
#define GSTAGE (4 * GARR)       // words per stage (Ahi,Alo,Bhi,Blo)
#define GEMM_SMEM (2 * GSTAGE * 4)

template <int MODE>
__global__ __launch_bounds__(256) void mma_gemm_kernel(
    const uint32_t* __restrict__ Ahi_g, const uint32_t* __restrict__ Alo_g,
    const uint32_t* __restrict__ Bhi_g, const uint32_t* __restrict__ Blo_g,
    const float* __restrict__ rope, float* __restrict__ out)
{
    extern __shared__ uint32_t sm[];
    const uint32_t sbase = smem_addr(sm);

    const int tid = threadIdx.x;
    const int lane = tid & 31;
    const int wid = tid >> 5;
    const int wm = wid & 1;
    const int wn = wid >> 1;
    const int m0 = blockIdx.y * 128;
    const int n0 = blockIdx.x * 128;

    float acc[4][4][4];
#pragma unroll
    for (int mt = 0; mt < 4; mt++)
#pragma unroll
        for (int nt = 0; nt < 4; nt++)
#pragma unroll
            for (int r = 0; r < 4; r++) acc[mt][nt][r] = 0.f;

    const int l8 = lane & 7, g = lane >> 3;
    const int offA = (l8 + ((g & 1) << 3)) * GSW + ((g & 2) ? 4 : 0);
    const int offB = (l8 + ((g >> 1) << 3)) * GSW + ((g & 1) << 2);

    const int crow = tid >> 1;       // 0..127
    const int chalf = tid & 1;       // word offset 16*chalf within 32-word row

    auto issue = [&](int ks, int st) {
        const uint32_t s0 = sbase + 4u * (st * GSTAGE + crow * GSW + chalf * 16);
        size_t aw;
        if (MODE == 0) {
            aw = (size_t)(m0 + crow) * 512 + ks * 32 + chalf * 16;
        } else {
            const int m = m0 + crow, b = m >> 11, t = m & 2047;
            aw = (((size_t)b * 16 + ks) * 2048 + t) * 32 + chalf * 16;
        }
        const size_t bw = (size_t)(n0 + crow) * 512 + ks * 32 + chalf * 16;
#pragma unroll
        for (int j = 0; j < 4; j++) {
            cpa16(s0 + 16u * j,                 Ahi_g + aw + 4 * j);
            cpa16(s0 + 4u * GARR + 16u * j,     Alo_g + aw + 4 * j);
            cpa16(s0 + 8u * GARR + 16u * j,     Bhi_g + bw + 4 * j);
            cpa16(s0 + 12u * GARR + 16u * j,    Blo_g + bw + 4 * j);
        }
    };

    issue(0, 0);
    CP_COMMIT();

    for (int ks = 0; ks < 16; ks++) {
        const int st = ks & 1;
        if (ks + 1 < 16) {
            issue(ks + 1, st ^ 1);
            CP_COMMIT();
            CP_WAIT1();
        } else {
            CP_WAIT0();
        }
        __syncthreads();

        const uint32_t aAhi = sbase + 4u * (st * GSTAGE);
        const uint32_t aAlo = aAhi + 4u * GARR;
        const uint32_t aBhi = aAhi + 8u * GARR;
        const uint32_t aBlo = aAhi + 12u * GARR;

#pragma unroll
        for (int kc = 0; kc < 4; kc++) {
            uint32_t afh[4][4], afl[4][4];
#pragma unroll
            for (int mt = 0; mt < 4; mt++) {
                const uint32_t wo = 4u * (offA + (wm * 64 + mt * 16) * GSW + 8 * kc);
                ldm_x4(afh[mt], aAhi + wo);
                ldm_x4(afl[mt], aAlo + wo);
            }
#pragma unroll
            for (int ntp = 0; ntp < 2; ntp++) {
                uint32_t bhf[4], blf[4];
                const uint32_t wo = 4u * (offB + (wn * 32 + ntp * 16) * GSW + 8 * kc);
                ldm_x4(bhf, aBhi + wo);
                ldm_x4(blf, aBlo + wo);
#pragma unroll
                for (int mt = 0; mt < 4; mt++) {
                    mma_bf16(acc[mt][2 * ntp], afh[mt], bhf);
                    mma_bf16(acc[mt][2 * ntp], afh[mt], blf);
                    mma_bf16(acc[mt][2 * ntp], afl[mt], bhf);
                    mma_bf16(acc[mt][2 * ntp + 1], afh[mt], bhf + 2);
                    mma_bf16(acc[mt][2 * ntp + 1], afh[mt], blf + 2);
                    mma_bf16(acc[mt][2 * ntp + 1], afl[mt], bhf + 2);
                }
            }
        }
        __syncthreads();
    }

    // Epilogue
    const int section = n0 >> 10;
    uint32_t* hiArr = (section == 0) ? g_Qhi : (section == 1) ? g_Khi : g_Vhi;
    uint32_t* loArr = (section == 0) ? g_Qlo : (section == 1) ? g_Klo : g_Vlo;
    const float qscale = (section == 0) ? 0.125f : 1.0f;
#pragma unroll
    for (int mt = 0; mt < 4; mt++) {
#pragma unroll
        for (int nt = 0; nt < 4; nt++) {
            const int cn = n0 + wn * 32 + nt * 8 + 2 * (lane & 3);
#pragma unroll
            for (int rr = 0; rr < 2; rr++) {
                const int m = m0 + wm * 64 + mt * 16 + (lane >> 2) + 8 * rr;
                const float v0 = acc[mt][nt][2 * rr];
                const float v1 = acc[mt][nt][2 * rr + 1];
                if (MODE == 0) {
                    const int t = m & 2047, b = m >> 11;
                    const int nn = cn & 1023;
                    float2 o;
                    if (section == 2) {
                        o = make_float2(v0, v1);
                    } else {
                        const float2 cs = ((const float2*)rope)[(size_t)t * 512 + (nn >> 1)];
                        o = make_float2(v0 * cs.x - v1 * cs.y, v0 * cs.y + v1 * cs.x);
                    }
                    uint32_t hw, lw;
                    split2(o.x * qscale, o.y * qscale, hw, lw);
                    const size_t widx =
                        ((((size_t)b * 16 + (nn >> 6)) * 2048 + t) * 64 + (nn & 63)) >> 1;
                    hiArr[widx] = hw;
                    loArr[widx] = lw;
                } else {
                    *(float2*)(out + (size_t)m * 1024 + cn) = make_float2(v0, v1);
                }
            }
        }
    }
}

// ---------------------------------------------------------------------------
// Flash attention, split-bf16 mma. BQ=128 (8 warps x m16), BK=64, dk=64.
// K/V tiles via cp.async double buffer; V fragments via ldmatrix.trans.
// Epilogue writes O pre-split (hi/lo) for the conversion-free proj GEMM.
// grid = (16 qblocks, 32 bh), 256 threads.
// ---------------------------------------------------------------------------
#define FSW 36
#define FARR (64 * FSW)
#define FSTAGE (4 * FARR)       // Khi,Klo,Vhi,Vlo
#define FLASH_SMEM (2 * FSTAGE * 4)

__global__ __launch_bounds__(256) void flash_mma_kernel()
{
    extern __shared__ uint32_t fsm[];
    const uint32_t fbase = smem_addr(fsm);

    const int tid = threadIdx.x;
    const int lane = tid & 31;
    const int w = tid >> 5;
    const int qb = blockIdx.x, bh = blockIdx.y;

    const int l8 = lane & 7, g = lane >> 3;
    const int offK = (l8 + ((g >> 1) << 3)) * FSW + ((g & 1) << 2);
    const int offV = (l8 + ((g & 1) << 3)) * FSW + ((g >> 1) << 2);

    // ---- Q fragments from global (pre-scaled by 1/8) ----
    uint32_t qh[4][4], ql[4][4];
    {
        const size_t qbase = ((size_t)bh * 2048 + qb * 128) * 32;
        const int r0 = w * 16 + (lane >> 2);
#pragma unroll
        for (int kc = 0; kc < 4; kc++) {
            const int wrd = 8 * kc + (lane & 3);
            qh[kc][0] = g_Qhi[qbase + (size_t)r0 * 32 + wrd];
            qh[kc][1] = g_Qhi[qbase + (size_t)(r0 + 8) * 32 + wrd];
            qh[kc][2] = g_Qhi[qbase + (size_t)r0 * 32 + wrd + 4];
            qh[kc][3] = g_Qhi[qbase + (size_t)(r0 + 8) * 32 + wrd + 4];
            ql[kc][0] = g_Qlo[qbase + (size_t)r0 * 32 + wrd];
            ql[kc][1] = g_Qlo[qbase + (size_t)(r0 + 8) * 32 + wrd];
            ql[kc][2] = g_Qlo[qbase + (size_t)r0 * 32 + wrd + 4];
            ql[kc][3] = g_Qlo[qbase + (size_t)(r0 + 8) * 32 + wrd + 4];
        }
    }

    float m0_ = -1e30f, m1_ = -1e30f, l0_ = 0.f, l1_ = 0.f;
    float o[8][4];
#pragma unroll
    for (int nt = 0; nt < 8; nt++)
#pragma unroll
        for (int r = 0; r < 4; r++) o[nt][r] = 0.f;

    const int cr = tid >> 2;          // row 0..63
    const int cq = tid & 3;           // word group: cq*8

    auto issue = [&](int kt, int st) {
        const size_t gw = ((size_t)bh * 2048 + kt * 64) * 32 + (size_t)cr * 32 + 8 * cq;
        const uint32_t s0 = fbase + 4u * (st * FSTAGE + cr * FSW + cq * 8);
        cpa16(s0,                        g_Khi + gw);
        cpa16(s0 + 16u,                  g_Khi + gw + 4);
        cpa16(s0 + 4u * FARR,            g_Klo + gw);
        cpa16(s0 + 4u * FARR + 16u,      g_Klo + gw + 4);
        cpa16(s0 + 8u * FARR,            g_Vhi + gw);
        cpa16(s0 + 8u * FARR + 16u,      g_Vhi + gw + 4);
        cpa16(s0 + 12u * FARR,           g_Vlo + gw);
        cpa16(s0 + 12u * FARR + 16u,     g_Vlo + gw + 4);
    };

    issue(0, 0);
    CP_COMMIT();

    for (int kt = 0; kt < 32; kt++) {
        const int st = kt & 1;
        if (kt + 1 < 32) {
            issue(kt + 1, st ^ 1);
            CP_COMMIT();
            CP_WAIT1();
        } else {
            CP_WAIT0();
        }
        __syncthreads();

        const uint32_t aKhi = fbase + 4u * (st * FSTAGE);
        const uint32_t aKlo = aKhi + 4u * FARR;
        const uint32_t aVhi = aKhi + 8u * FARR;
        const uint32_t aVlo = aKhi + 12u * FARR;

        // ---- S = (Q/8) @ K^T ----
        float s[8][4];
#pragma unroll
        for (int nt = 0; nt < 8; nt++)
#pragma unroll
            for (int r = 0; r < 4; r++) s[nt][r] = 0.f;
#pragma unroll
        for (int kc = 0; kc < 4; kc++) {
#pragma unroll
            for (int ntp = 0; ntp < 4; ntp++) {
                uint32_t bhf[4], blf[4];
                const uint32_t wo = 4u * (offK + ntp * 16 * FSW + 8 * kc);
                ldm_x4(bhf, aKhi + wo);
                ldm_x4(blf, aKlo + wo);
                mma_bf16(s[2 * ntp], qh[kc], bhf);
                mma_bf16(s[2 * ntp], qh[kc], blf);
                mma_bf16(s[2 * ntp], ql[kc], bhf);
                mma_bf16(s[2 * ntp + 1], qh[kc], bhf + 2);
                mma_bf16(s[2 * ntp + 1], qh[kc], blf + 2);
                mma_bf16(s[2 * ntp + 1], ql[kc], bhf + 2);
            }
        }

        // ---- online softmax ----
        float ml0 = -1e30f, ml1 = -1e30f;
#pragma unroll
        for (int nt = 0; nt < 8; nt++) {
            ml0 = fmaxf(ml0, fmaxf(s[nt][0], s[nt][1]));
            ml1 = fmaxf(ml1, fmaxf(s[nt][2], s[nt][3]));
        }
#pragma unroll
        for (int off = 1; off <= 2; off <<= 1) {
            ml0 = fmaxf(ml0, __shfl_xor_sync(0xffffffffu, ml0, off));
            ml1 = fmaxf(ml1, __shfl_xor_sync(0xffffffffu, ml1, off));
        }
        const float mn0 = fmaxf(m0_, ml0), mn1 = fmaxf(m1_, ml1);
        const float a0 = __expf(m0_ - mn0), a1 = __expf(m1_ - mn1);
        m0_ = mn0; m1_ = mn1;
        float rs0 = 0.f, rs1 = 0.f;
#pragma unroll
        for (int nt = 0; nt < 8; nt++) {
            s[nt][0] = __expf(s[nt][0] - mn0);
            s[nt][1] = __expf(s[nt][1] - mn0);
            s[nt][2] = __expf(s[nt][2] - mn1);
            s[nt][3] = __expf(s[nt][3] - mn1);
            rs0 += s[nt][0] + s[nt][1];
            rs1 += s[nt][2] + s[nt][3];
        }
#pragma unroll
        for (int off = 1; off <= 2; off <<= 1) {
            rs0 += __shfl_xor_sync(0xffffffffu, rs0, off);
            rs1 += __shfl_xor_sync(0xffffffffu, rs1, off);
        }
        l0_ = l0_ * a0 + rs0;
        l1_ = l1_ * a1 + rs1;
#pragma unroll
        for (int nt = 0; nt < 8; nt++) {
            o[nt][0] *= a0; o[nt][1] *= a0;
            o[nt][2] *= a1; o[nt][3] *= a1;
        }

        // ---- P fragments (in-register) ----
        uint32_t ph[4][4], pl[4][4];
#pragma unroll
        for (int kc = 0; kc < 4; kc++) {
            split2(s[2 * kc][0], s[2 * kc][1], ph[kc][0], pl[kc][0]);
            split2(s[2 * kc][2], s[2 * kc][3], ph[kc][1], pl[kc][1]);
            split2(s[2 * kc + 1][0], s[2 * kc + 1][1], ph[kc][2], pl[kc][2]);
            split2(s[2 * kc + 1][2], s[2 * kc + 1][3], ph[kc][3], pl[kc][3]);
        }

        // ---- O += P @ V ----
#pragma unroll
        for (int kc = 0; kc < 4; kc++) {
#pragma unroll
            for (int ntp = 0; ntp < 4; ntp++) {
                uint32_t vhf[4], vlf[4];
                const uint32_t wo = 4u * (offV + kc * 16 * FSW + ntp * 8);
                ldm_x4t(vhf, aVhi + wo);
                ldm_x4t(vlf, aVlo + wo);
                mma_bf16(o[2 * ntp], ph[kc], vhf);
                mma_bf16(o[2 * ntp], ph[kc], vlf);
                mma_bf16(o[2 * ntp], pl[kc], vhf);
                mma_bf16(o[2 * ntp + 1], ph[kc], vhf + 2);
                mma_bf16(o[2 * ntp + 1], ph[kc], vlf + 2);
                mma_bf16(o[2 * ntp + 1], pl[kc], vhf + 2);
            }
        }
        __syncthreads();
    }

    // ---- normalize + store pre-split O (head-major words) ----
    const float inv0 = 1.f / l0_, inv1 = 1.f / l1_;
    const int qrow = qb * 128 + w * 16 + (lane >> 2);
    const size_t ob = ((size_t)bh * 2048 + qrow) * 32;
#pragma unroll
    for (int nt = 0; nt < 8; nt++) {
        const int wd = nt * 4 + (lane & 3);
        uint32_t hw, lw;
        split2(o[nt][0] * inv0, o[nt][1] * inv0, hw, lw);
        g_Ohi[ob + wd] = hw;
        g_Olo[ob + wd] = lw;
        split2(o[nt][2] * inv1, o[nt][3] * inv1, hw, lw);
        g_Ohi[ob + 8 * 32 + wd] = hw;
        g_Olo[ob + 8 * 32 + wd] = lw;
    }
}

// ---------------------------------------------------------------------------
extern "C" void kernel_launch(void* const* d_in, const int* in_sizes, int n_in,
                              void* d_out, int out_size)
{
    const float* x      = (const float*)d_in[0];   // (2, 2048, 1024)
    const float* rope   = (const float*)d_in[1];   // (2048, 512, 2)
    const float* w_qkv  = (const float*)d_in[2];   // (3072, 1024)
    const float* w_proj = (const float*)d_in[3];   // (1024, 1024)
    float* out = (float*)d_out;                    // (2, 2048, 1024)

    uint4 *xhi, *xlo, *wqhi, *wqlo, *wphi, *wplo;
    cudaGetSymbolAddress((void**)&xhi, g_Xhi);
    cudaGetSymbolAddress((void**)&xlo, g_Xlo);
    cudaGetSymbolAddress((void**)&wqhi, g_WQhi);
    cudaGetSymbolAddress((void**)&wqlo, g_WQlo);
    cudaGetSymbolAddress((void**)&wphi, g_WPhi);
    cudaGetSymbolAddress((void**)&wplo, g_WPlo);
    const uint32_t *xhi_c = (const uint32_t*)xhi, *xlo_c = (const uint32_t*)xlo;
    const uint32_t *wqhi_c = (const uint32_t*)wqhi, *wqlo_c = (const uint32_t*)wqlo;
    const uint32_t *wphi_c = (const uint32_t*)wphi, *wplo_c = (const uint32_t*)wplo;
    const uint32_t *ohi_c, *olo_c;
    cudaGetSymbolAddress((void**)&ohi_c, g_Ohi);
    cudaGetSymbolAddress((void**)&olo_c, g_Olo);

    cudaFuncSetAttribute(mma_gemm_kernel<0>,
                         cudaFuncAttributeMaxDynamicSharedMemorySize, GEMM_SMEM);
    cudaFuncSetAttribute(mma_gemm_kernel<1>,
                         cudaFuncAttributeMaxDynamicSharedMemorySize, GEMM_SMEM);
    cudaFuncSetAttribute(flash_mma_kernel,
                         cudaFuncAttributeMaxDynamicSharedMemorySize, FLASH_SMEM);

    presplit_kernel<<<2048, 256>>>((const float4*)x, xhi, xlo);
    presplit_kernel<<<1536, 256>>>((const float4*)w_qkv, wqhi, wqlo);
    presplit_kernel<<<512, 256>>>((const float4*)w_proj, wphi, wplo);

    mma_gemm_kernel<0><<<dim3(24, 32), 256, GEMM_SMEM>>>(
        xhi_c, xlo_c, wqhi_c, wqlo_c, rope, nullptr);
    flash_mma_kernel<<<dim3(16, 32), 256, FLASH_SMEM>>>();
    mma_gemm_kernel<1><<<dim3(8, 32), 256, GEMM_SMEM>>>(
        ohi_c, olo_c, wphi_c, wplo_c, nullptr, out);
}

// round 11
// speedup vs baseline: 1.0500x; 1.0500x over previous
#include <cuda_runtime.h>
#include <cuda_bf16.h>
#include <cstdint>

// Problem constants: B=2, T=2048, D=1024, H=16, dk=64
// Pre-split hi/lo bf16-pair word arrays (1 word = 2 bf16 = one fp32 lane pair)
__device__ uint32_t g_Xhi[2097152],  g_Xlo[2097152];    // x       (B,T,D)
__device__ uint32_t g_WQhi[1572864], g_WQlo[1572864];   // w_qkv   (3D,D)
__device__ uint32_t g_WPhi[524288],  g_WPlo[524288];    // w_proj  (D,D)
__device__ uint32_t g_Qhi[2097152],  g_Qlo[2097152];    // head-major (B,H,T,dk)
__device__ uint32_t g_Khi[2097152],  g_Klo[2097152];
__device__ uint32_t g_Vhi[2097152],  g_Vlo[2097152];
__device__ uint32_t g_Ohi[2097152],  g_Olo[2097152];

// ---------------------------------------------------------------------------
// Helpers
// ---------------------------------------------------------------------------
__device__ __forceinline__ void split2(float f0, float f1, uint32_t& hi, uint32_t& lo) {
    __nv_bfloat162 h = __floats2bfloat162_rn(f0, f1);
    float r0 = f0 - __bfloat162float(h.x);
    float r1 = f1 - __bfloat162float(h.y);
    __nv_bfloat162 l = __floats2bfloat162_rn(r0, r1);
    hi = *(uint32_t*)&h;
    lo = *(uint32_t*)&l;
}
__device__ __forceinline__ void mma_bf16(float* d, const uint32_t* a, const uint32_t* b) {
    asm volatile(
        "mma.sync.aligned.m16n8k16.row.col.f32.bf16.bf16.f32 "
        "{%0,%1,%2,%3}, {%4,%5,%6,%7}, {%8,%9}, {%0,%1,%2,%3};"
        : "+f"(d[0]), "+f"(d[1]), "+f"(d[2]), "+f"(d[3])
        : "r"(a[0]), "r"(a[1]), "r"(a[2]), "r"(a[3]), "r"(b[0]), "r"(b[1]));
}
__device__ __forceinline__ void ldm_x4(uint32_t* r, uint32_t addr) {
    asm volatile("ldmatrix.sync.aligned.m8n8.x4.shared.b16 {%0,%1,%2,%3}, [%4];"
                 : "=r"(r[0]), "=r"(r[1]), "=r"(r[2]), "=r"(r[3]) : "r"(addr));
}
__device__ __forceinline__ void ldm_x4t(uint32_t* r, uint32_t addr) {
    asm volatile("ldmatrix.sync.aligned.m8n8.x4.trans.shared.b16 {%0,%1,%2,%3}, [%4];"
                 : "=r"(r[0]), "=r"(r[1]), "=r"(r[2]), "=r"(r[3]) : "r"(addr));
}
__device__ __forceinline__ uint32_t smem_addr(const void* p) {
    return (uint32_t)__cvta_generic_to_shared(p);
}

// ---------------------------------------------------------------------------
// Pre-split: fp32 -> hi/lo bf16-pair words. Each thread handles 8 floats.
// ---------------------------------------------------------------------------
__global__ __launch_bounds__(256) void presplit_kernel(
    const float4* __restrict__ src, uint4* __restrict__ hi, uint4* __restrict__ lo)
{
    const int i = blockIdx.x * 256 + threadIdx.x;
    const float4 a = src[2 * i], b = src[2 * i + 1];
    uint4 h, l;
    split2(a.x, a.y, h.x, l.x);
    split2(a.z, a.w, h.y, l.y);
    split2(b.x, b.y, h.z, l.z);
    split2(b.z, b.w, h.w, l.w);
    hi[i] = h;
    lo[i] = l;
}

// ---------------------------------------------------------------------------
// GEMM: out[m,n] = sum_k A[m,k]*W[n,k], split-bf16 (3 mma terms).
// CTA tile 128x128, 512 threads / 16 warps, warp tile 32x32.
// K-chunk 32 (16 words), register-prefetch single-buffer; shared stride 20
// words (ldmatrix conflict-free). Inputs pre-split -> staging is pure copies.
// MODE 0: A = pre-split x; epilogue RoPE + split-bf16 Q/K/V store (Q * 1/8).
// MODE 1: A = pre-split O (head-major); epilogue fp32 store to out.
// ---------------------------------------------------------------------------
#define GS 20

template <int MODE>
__global__ __launch_bounds__(512) void mma_gemm_kernel(
    const uint32_t* __restrict__ Ahi_g, const uint32_t* __restrict__ Alo_g,
    const uint32_t* __restrict__ Bhi_g, const uint32_t* __restrict__ Blo_g,
    const float* __restrict__ rope, float* __restrict__ out)
{
    __shared__ uint32_t Ahi[128 * GS], Alo[128 * GS];
    __shared__ uint32_t Bhi[128 * GS], Blo[128 * GS];

    const int tid = threadIdx.x;
    const int lane = tid & 31;
    const int wid = tid >> 5;
    const int wm = wid & 3;        // m offset 32*wm
    const int wn = wid >> 2;       // n offset 32*wn
    const int m0 = blockIdx.y * 128;
    const int n0 = blockIdx.x * 128;

    float acc[2][4][4];
#pragma unroll
    for (int mt = 0; mt < 2; mt++)
#pragma unroll
        for (int nt = 0; nt < 4; nt++)
#pragma unroll
            for (int r = 0; r < 4; r++) acc[mt][nt][r] = 0.f;

    const int l8 = lane & 7, g = lane >> 3;
    const int offA = (l8 + ((g & 1) << 3)) * GS + ((g & 2) ? 4 : 0);
    const int offB = (l8 + ((g >> 1) << 3)) * GS + ((g & 1) << 2);
    const uint32_t aAhi = smem_addr(Ahi), aAlo = smem_addr(Alo);
    const uint32_t aBhi = smem_addr(Bhi), aBlo = smem_addr(Blo);

    const int crow = tid >> 2;       // 0..127
    const int cseg = tid & 3;        // uint4 segment (4 words)

    auto aAddr = [&](int ks) -> size_t {
        const int kw = ks * 16 + 4 * cseg;
        if (MODE == 0) {
            return (size_t)(m0 + crow) * 512 + kw;
        } else {
            const int m = m0 + crow, b = m >> 11, t = m & 2047;
            return (((size_t)b * 16 + (kw >> 5)) * 2048 + t) * 32 + (kw & 31);
        }
    };
    auto bAddr = [&](int ks) -> size_t {
        return (size_t)(n0 + crow) * 512 + ks * 16 + 4 * cseg;
    };

    uint4 pah, pal, pbh, pbl;
    {
        const size_t aw = aAddr(0), bw = bAddr(0);
        pah = *(const uint4*)(Ahi_g + aw);
        pal = *(const uint4*)(Alo_g + aw);
        pbh = *(const uint4*)(Bhi_g + bw);
        pbl = *(const uint4*)(Blo_g + bw);
    }

    for (int ks = 0; ks < 32; ks++) {
        __syncthreads();
        const int sw = crow * GS + 4 * cseg;
        *(uint4*)&Ahi[sw] = pah;
        *(uint4*)&Alo[sw] = pal;
        *(uint4*)&Bhi[sw] = pbh;
        *(uint4*)&Blo[sw] = pbl;
        __syncthreads();
        if (ks + 1 < 32) {
            const size_t aw = aAddr(ks + 1), bw = bAddr(ks + 1);
            pah = *(const uint4*)(Ahi_g + aw);
            pal = *(const uint4*)(Alo_g + aw);
            pbh = *(const uint4*)(Bhi_g + bw);
            pbl = *(const uint4*)(Blo_g + bw);
        }
#pragma unroll
        for (int kc = 0; kc < 2; kc++) {
            uint32_t afh[2][4], afl[2][4];
#pragma unroll
            for (int mt = 0; mt < 2; mt++) {
                const uint32_t wo = 4u * (offA + (wm * 32 + mt * 16) * GS + 8 * kc);
                ldm_x4(afh[mt], aAhi + wo);
                ldm_x4(afl[mt], aAlo + wo);
            }
#pragma unroll
            for (int np = 0; np < 2; np++) {
                uint32_t bhf[4], blf[4];
                const uint32_t wo = 4u * (offB + (wn * 32 + np * 16) * GS + 8 * kc);
                ldm_x4(bhf, aBhi + wo);
                ldm_x4(blf, aBlo + wo);
#pragma unroll
                for (int mt = 0; mt < 2; mt++) {
                    mma_bf16(acc[mt][2 * np], afh[mt], bhf);
                    mma_bf16(acc[mt][2 * np], afh[mt], blf);
                    mma_bf16(acc[mt][2 * np], afl[mt], bhf);
                    mma_bf16(acc[mt][2 * np + 1], afh[mt], bhf + 2);
                    mma_bf16(acc[mt][2 * np + 1], afh[mt], blf + 2);
                    mma_bf16(acc[mt][2 * np + 1], afl[mt], bhf + 2);
                }
            }
        }
    }

    // Epilogue
    const int section = n0 >> 10;
    uint32_t* hiArr = (section == 0) ? g_Qhi : (section == 1) ? g_Khi : g_Vhi;
    uint32_t* loArr = (section == 0) ? g_Qlo : (section == 1) ? g_Klo : g_Vlo;
    const float qscale = (section == 0) ? 0.125f : 1.0f;
#pragma unroll
    for (int mt = 0; mt < 2; mt++) {
#pragma unroll
        for (int nt = 0; nt < 4; nt++) {
            const int cn = n0 + wn * 32 + nt * 8 + 2 * (lane & 3);
#pragma unroll
            for (int rr = 0; rr < 2; rr++) {
                const int m = m0 + wm * 32 + mt * 16 + (lane >> 2) + 8 * rr;
                const float v0 = acc[mt][nt][2 * rr];
                const float v1 = acc[mt][nt][2 * rr + 1];
                if (MODE == 0) {
                    const int t = m & 2047, b = m >> 11;
                    const int nn = cn & 1023;
                    float2 o;
                    if (section == 2) {
                        o = make_float2(v0, v1);
                    } else {
                        const float2 cs = ((const float2*)rope)[(size_t)t * 512 + (nn >> 1)];
                        o = make_float2(v0 * cs.x - v1 * cs.y, v0 * cs.y + v1 * cs.x);
                    }
                    uint32_t hw, lw;
                    split2(o.x * qscale, o.y * qscale, hw, lw);
                    const size_t widx =
                        ((((size_t)b * 16 + (nn >> 6)) * 2048 + t) * 64 + (nn & 63)) >> 1;
                    hiArr[widx] = hw;
                    loArr[widx] = lw;
                } else {
                    *(float2*)(out + (size_t)m * 1024 + cn) = make_float2(v0, v1);
                }
            }
        }
    }
}

// ---------------------------------------------------------------------------
// Flash attention, split-bf16 mma. BQ=128 (8 warps x m16), BK=64, dk=64.
// Q frags from global (pre-scaled 1/8); K/V staged via uint4 copies;
// V fragments via ldmatrix.trans. Epilogue stores O pre-split for proj.
// grid = (16 qblocks, 32 bh), 256 threads.
// ---------------------------------------------------------------------------
#define FS 36

__global__ __launch_bounds__(256) void flash_mma_kernel()
{
    __shared__ uint32_t Khi[64 * FS], Klo[64 * FS];
    __shared__ uint32_t Vhi[64 * FS], Vlo[64 * FS];

    const int tid = threadIdx.x;
    const int lane = tid & 31;
    const int w = tid >> 5;
    const int qb = blockIdx.x, bh = blockIdx.y;

    const int l8 = lane & 7, g = lane >> 3;
    const int offK = (l8 + ((g >> 1) << 3)) * FS + ((g & 1) << 2);
    const int offV = (l8 + ((g & 1) << 3)) * FS + ((g >> 1) << 2);
    const uint32_t aKhi = smem_addr(Khi), aKlo = smem_addr(Klo);
    const uint32_t aVhi = smem_addr(Vhi), aVlo = smem_addr(Vlo);

    // ---- Q fragments from global ----
    uint32_t qh[4][4], ql[4][4];
    {
        const size_t qbase = ((size_t)bh * 2048 + qb * 128) * 32;
        const int r0 = w * 16 + (lane >> 2);
#pragma unroll
        for (int kc = 0; kc < 4; kc++) {
            const int wrd = 8 * kc + (lane & 3);
            qh[kc][0] = g_Qhi[qbase + (size_t)r0 * 32 + wrd];
            qh[kc][1] = g_Qhi[qbase + (size_t)(r0 + 8) * 32 + wrd];
            qh[kc][2] = g_Qhi[qbase + (size_t)r0 * 32 + wrd + 4];
            qh[kc][3] = g_Qhi[qbase + (size_t)(r0 + 8) * 32 + wrd + 4];
            ql[kc][0] = g_Qlo[qbase + (size_t)r0 * 32 + wrd];
            ql[kc][1] = g_Qlo[qbase + (size_t)(r0 + 8) * 32 + wrd];
            ql[kc][2] = g_Qlo[qbase + (size_t)r0 * 32 + wrd + 4];
            ql[kc][3] = g_Qlo[qbase + (size_t)(r0 + 8) * 32 + wrd + 4];
        }
    }

    float m0_ = -1e30f, m1_ = -1e30f, l0_ = 0.f, l1_ = 0.f;
    float o[8][4];
#pragma unroll
    for (int nt = 0; nt < 8; nt++)
#pragma unroll
        for (int r = 0; r < 4; r++) o[nt][r] = 0.f;

    const int cr = tid >> 2;
    const int cq = tid & 3;

    for (int kt = 0; kt < 32; kt++) {
        __syncthreads();
        {
            const size_t gw = ((size_t)bh * 2048 + kt * 64) * 32 + (size_t)cr * 32 + 8 * cq;
            const int sw = cr * FS + 8 * cq;
            *(uint4*)&Khi[sw]     = *(const uint4*)&g_Khi[gw];
            *(uint4*)&Khi[sw + 4] = *(const uint4*)&g_Khi[gw + 4];
            *(uint4*)&Klo[sw]     = *(const uint4*)&g_Klo[gw];
            *(uint4*)&Klo[sw + 4] = *(const uint4*)&g_Klo[gw + 4];
            *(uint4*)&Vhi[sw]     = *(const uint4*)&g_Vhi[gw];
            *(uint4*)&Vhi[sw + 4] = *(const uint4*)&g_Vhi[gw + 4];
            *(uint4*)&Vlo[sw]     = *(const uint4*)&g_Vlo[gw];
            *(uint4*)&Vlo[sw + 4] = *(const uint4*)&g_Vlo[gw + 4];
        }
        __syncthreads();

        // ---- S = (Q/8) @ K^T ----
        float s[8][4];
#pragma unroll
        for (int nt = 0; nt < 8; nt++)
#pragma unroll
            for (int r = 0; r < 4; r++) s[nt][r] = 0.f;
#pragma unroll
        for (int kc = 0; kc < 4; kc++) {
#pragma unroll
            for (int ntp = 0; ntp < 4; ntp++) {
                uint32_t bhf[4], blf[4];
                const uint32_t wo = 4u * (offK + ntp * 16 * FS + 8 * kc);
                ldm_x4(bhf, aKhi + wo);
                ldm_x4(blf, aKlo + wo);
                mma_bf16(s[2 * ntp], qh[kc], bhf);
                mma_bf16(s[2 * ntp], qh[kc], blf);
                mma_bf16(s[2 * ntp], ql[kc], bhf);
                mma_bf16(s[2 * ntp + 1], qh[kc], bhf + 2);
                mma_bf16(s[2 * ntp + 1], qh[kc], blf + 2);
                mma_bf16(s[2 * ntp + 1], ql[kc], bhf + 2);
            }
        }

        // ---- online softmax ----
        float ml0 = -1e30f, ml1 = -1e30f;
#pragma unroll
        for (int nt = 0; nt < 8; nt++) {
            ml0 = fmaxf(ml0, fmaxf(s[nt][0], s[nt][1]));
            ml1 = fmaxf(ml1, fmaxf(s[nt][2], s[nt][3]));
        }
#pragma unroll
        for (int off = 1; off <= 2; off <<= 1) {
            ml0 = fmaxf(ml0, __shfl_xor_sync(0xffffffffu, ml0, off));
            ml1 = fmaxf(ml1, __shfl_xor_sync(0xffffffffu, ml1, off));
        }
        const float mn0 = fmaxf(m0_, ml0), mn1 = fmaxf(m1_, ml1);
        const float a0 = __expf(m0_ - mn0), a1 = __expf(m1_ - mn1);
        m0_ = mn0; m1_ = mn1;
        float rs0 = 0.f, rs1 = 0.f;
#pragma unroll
        for (int nt = 0; nt < 8; nt++) {
            s[nt][0] = __expf(s[nt][0] - mn0);
            s[nt][1] = __expf(s[nt][1] - mn0);
            s[nt][2] = __expf(s[nt][2] - mn1);
            s[nt][3] = __expf(s[nt][3] - mn1);
            rs0 += s[nt][0] + s[nt][1];
            rs1 += s[nt][2] + s[nt][3];
        }
#pragma unroll
        for (int off = 1; off <= 2; off <<= 1) {
            rs0 += __shfl_xor_sync(0xffffffffu, rs0, off);
            rs1 += __shfl_xor_sync(0xffffffffu, rs1, off);
        }
        l0_ = l0_ * a0 + rs0;
        l1_ = l1_ * a1 + rs1;
#pragma unroll
        for (int nt = 0; nt < 8; nt++) {
            o[nt][0] *= a0; o[nt][1] *= a0;
            o[nt][2] *= a1; o[nt][3] *= a1;
        }

        // ---- P fragments (in-register) ----
        uint32_t ph[4][4], pl[4][4];
#pragma unroll
        for (int kc = 0; kc < 4; kc++) {
            split2(s[2 * kc][0], s[2 * kc][1], ph[kc][0], pl[kc][0]);
            split2(s[2 * kc][2], s[2 * kc][3], ph[kc][1], pl[kc][1]);
            split2(s[2 * kc + 1][0], s[2 * kc + 1][1], ph[kc][2], pl[kc][2]);
            split2(s[2 * kc + 1][2], s[2 * kc + 1][3], ph[kc][3], pl[kc][3]);
        }

        // ---- O += P @ V ----
#pragma unroll
        for (int kc = 0; kc < 4; kc++) {
#pragma unroll
            for (int ntp = 0; ntp < 4; ntp++) {
                uint32_t vhf[4], vlf[4];
                const uint32_t wo = 4u * (offV + kc * 16 * FS + ntp * 8);
                ldm_x4t(vhf, aVhi + wo);
                ldm_x4t(vlf, aVlo + wo);
                mma_bf16(o[2 * ntp], ph[kc], vhf);
                mma_bf16(o[2 * ntp], ph[kc], vlf);
                mma_bf16(o[2 * ntp], pl[kc], vhf);
                mma_bf16(o[2 * ntp + 1], ph[kc], vhf + 2);
                mma_bf16(o[2 * ntp + 1], ph[kc], vlf + 2);
                mma_bf16(o[2 * ntp + 1], pl[kc], vhf + 2);
            }
        }
    }

    // ---- normalize + store pre-split O (head-major words) ----
    const float inv0 = 1.f / l0_, inv1 = 1.f / l1_;
    const int qrow = qb * 128 + w * 16 + (lane >> 2);
    const size_t ob = ((size_t)bh * 2048 + qrow) * 32;
#pragma unroll
    for (int nt = 0; nt < 8; nt++) {
        const int wd = nt * 4 + (lane & 3);
        uint32_t hw, lw;
        split2(o[nt][0] * inv0, o[nt][1] * inv0, hw, lw);
        g_Ohi[ob + wd] = hw;
        g_Olo[ob + wd] = lw;
        split2(o[nt][2] * inv1, o[nt][3] * inv1, hw, lw);
        g_Ohi[ob + 8 * 32 + wd] = hw;
        g_Olo[ob + 8 * 32 + wd] = lw;
    }
}

// ---------------------------------------------------------------------------
extern "C" void kernel_launch(void* const* d_in, const int* in_sizes, int n_in,
                              void* d_out, int out_size)
{
    const float* x      = (const float*)d_in[0];   // (2, 2048, 1024)
    const float* rope   = (const float*)d_in[1];   // (2048, 512, 2)
    const float* w_qkv  = (const float*)d_in[2];   // (3072, 1024)
    const float* w_proj = (const float*)d_in[3];   // (1024, 1024)
    float* out = (float*)d_out;                    // (2, 2048, 1024)

    uint4 *xhi, *xlo, *wqhi, *wqlo, *wphi, *wplo;
    cudaGetSymbolAddress((void**)&xhi, g_Xhi);
    cudaGetSymbolAddress((void**)&xlo, g_Xlo);
    cudaGetSymbolAddress((void**)&wqhi, g_WQhi);
    cudaGetSymbolAddress((void**)&wqlo, g_WQlo);
    cudaGetSymbolAddress((void**)&wphi, g_WPhi);
    cudaGetSymbolAddress((void**)&wplo, g_WPlo);
    uint32_t *ohi, *olo;
    cudaGetSymbolAddress((void**)&ohi, g_Ohi);
    cudaGetSymbolAddress((void**)&olo, g_Olo);

    presplit_kernel<<<2048, 256>>>((const float4*)x, xhi, xlo);
    presplit_kernel<<<1536, 256>>>((const float4*)w_qkv, wqhi, wqlo);
    presplit_kernel<<<512, 256>>>((const float4*)w_proj, wphi, wplo);

    mma_gemm_kernel<0><<<dim3(24, 32), 512>>>(
        (const uint32_t*)xhi, (const uint32_t*)xlo,
        (const uint32_t*)wqhi, (const uint32_t*)wqlo, rope, nullptr);
    flash_mma_kernel<<<dim3(16, 32), 256>>>();
    mma_gemm_kernel<1><<<dim3(8, 32), 512>>>(
        ohi, olo, (const uint32_t*)wphi, (const uint32_t*)wplo, nullptr, out);
}

// round 14
// speedup vs baseline: 1.0822x; 1.0307x over previous
#include <cuda_runtime.h>
#include <cuda_bf16.h>
#include <cstdint>

// Problem constants: B=2, T=2048, D=1024, H=16, dk=64
// Pre-split hi/lo bf16-pair word arrays (1 word = 2 bf16 = one fp32 lane pair)
__device__ uint32_t g_Xhi[2097152],  g_Xlo[2097152];    // x       (B,T,D)
__device__ uint32_t g_WQhi[1572864], g_WQlo[1572864];   // w_qkv   (3D,D)
__device__ uint32_t g_WPhi[524288],  g_WPlo[524288];    // w_proj  (D,D)
__device__ uint32_t g_Qhi[2097152],  g_Qlo[2097152];    // head-major (B,H,T,dk)
__device__ uint32_t g_Khi[2097152],  g_Klo[2097152];
__device__ uint32_t g_Vhi[2097152],  g_Vlo[2097152];
__device__ uint32_t g_Ohi[2097152],  g_Olo[2097152];

// ---------------------------------------------------------------------------
// Helpers
// ---------------------------------------------------------------------------
__device__ __forceinline__ void split2(float f0, float f1, uint32_t& hi, uint32_t& lo) {
    __nv_bfloat162 h = __floats2bfloat162_rn(f0, f1);
    float r0 = f0 - __bfloat162float(h.x);
    float r1 = f1 - __bfloat162float(h.y);
    __nv_bfloat162 l = __floats2bfloat162_rn(r0, r1);
    hi = *(uint32_t*)&h;
    lo = *(uint32_t*)&l;
}
__device__ __forceinline__ void mma_bf16(float* d, const uint32_t* a, const uint32_t* b) {
    asm volatile(
        "mma.sync.aligned.m16n8k16.row.col.f32.bf16.bf16.f32 "
        "{%0,%1,%2,%3}, {%4,%5,%6,%7}, {%8,%9}, {%0,%1,%2,%3};"
        : "+f"(d[0]), "+f"(d[1]), "+f"(d[2]), "+f"(d[3])
        : "r"(a[0]), "r"(a[1]), "r"(a[2]), "r"(a[3]), "r"(b[0]), "r"(b[1]));
}
__device__ __forceinline__ void ldm_x4(uint32_t* r, uint32_t addr) {
    asm volatile("ldmatrix.sync.aligned.m8n8.x4.shared.b16 {%0,%1,%2,%3}, [%4];"
                 : "=r"(r[0]), "=r"(r[1]), "=r"(r[2]), "=r"(r[3]) : "r"(addr));
}
__device__ __forceinline__ void ldm_x4t(uint32_t* r, uint32_t addr) {
    asm volatile("ldmatrix.sync.aligned.m8n8.x4.trans.shared.b16 {%0,%1,%2,%3}, [%4];"
                 : "=r"(r[0]), "=r"(r[1]), "=r"(r[2]), "=r"(r[3]) : "r"(addr));
}
__device__ __forceinline__ uint32_t smem_addr(const void* p) {
    return (uint32_t)__cvta_generic_to_shared(p);
}
__device__ __forceinline__ void cpa16(uint32_t saddr, const void* g) {
    asm volatile("cp.async.cg.shared.global [%0], [%1], 16;" :: "r"(saddr), "l"(g));
}
#define CP_COMMIT() asm volatile("cp.async.commit_group;" ::: "memory")
#define CP_WAIT0()  asm volatile("cp.async.wait_group 0;" ::: "memory")
#define CP_WAIT1()  asm volatile("cp.async.wait_group 1;" ::: "memory")

// ---------------------------------------------------------------------------
// Pre-split: fp32 -> hi/lo bf16-pair words. Each thread handles 8 floats.
// ---------------------------------------------------------------------------
__global__ __launch_bounds__(256) void presplit_kernel(
    const float4* __restrict__ src, uint4* __restrict__ hi, uint4* __restrict__ lo)
{
    const int i = blockIdx.x * 256 + threadIdx.x;
    const float4 a = src[2 * i], b = src[2 * i + 1];
    uint4 h, l;
    split2(a.x, a.y, h.x, l.x);
    split2(a.z, a.w, h.y, l.y);
    split2(b.x, b.y, h.z, l.z);
    split2(b.z, b.w, h.w, l.w);
    hi[i] = h;
    lo[i] = l;
}

// ---------------------------------------------------------------------------
// GEMM: out[m,n] = sum_k A[m,k]*W[n,k], split-bf16 (3 mma terms).
// CTA tile 128x256, 8 warps (2m x 4n), WARP TILE 64x64 -> 85 B smem / mma.
// K staged in 32 chunks of 32 floats (16 words), cp.async double-buffered,
// stride 20 words (ldmatrix conflict-free).
// MODE 0: A = pre-split x; epilogue RoPE + split-bf16 Q/K/V store (Q * 1/8).
// MODE 1: A = pre-split O (head-major); epilogue fp32 store to out.
// ---------------------------------------------------------------------------
#define GS 20
#define AW (128 * GS)                 // words per A array (2560)
#define BW (256 * GS)                 // words per B array (5120)
#define STW (2 * AW + 2 * BW)         // words per stage (15360)
#define GEMM_SMEM (2 * STW * 4)       // 122880 B
#define NKS 32                        // K stages: 32 x 32 floats = 1024

template <int MODE>
__global__ __launch_bounds__(256) void mma_gemm_kernel(
    const uint32_t* __restrict__ Ahi_g, const uint32_t* __restrict__ Alo_g,
    const uint32_t* __restrict__ Bhi_g, const uint32_t* __restrict__ Blo_g,
    const float* __restrict__ rope, float* __restrict__ out)
{
    extern __shared__ uint32_t sm[];
    const uint32_t sbase = smem_addr(sm);

    const int tid = threadIdx.x;
    const int lane = tid & 31;
    const int wid = tid >> 5;
    const int wm = wid & 1;        // m offset 64*wm
    const int wn = wid >> 1;       // n offset 64*wn
    const int m0 = blockIdx.y * 128;
    const int n0 = blockIdx.x * 256;

    float acc[4][8][4];
#pragma unroll
    for (int mt = 0; mt < 4; mt++)
#pragma unroll
        for (int nt = 0; nt < 8; nt++)
#pragma unroll
            for (int r = 0; r < 4; r++) acc[mt][nt][r] = 0.f;

    const int l8 = lane & 7, g = lane >> 3;
    const int offA = (l8 + ((g & 1) << 3)) * GS + ((g & 2) ? 4 : 0);
    const int offB = (l8 + ((g >> 1) << 3)) * GS + ((g & 1) << 2);

    auto issue = [&](int ks, int st) {
        const uint32_t sb = sbase + 4u * (st * STW);
        // A arrays: 128 rows x 4 segs = 512 uint4 tasks -> 2 per thread
#pragma unroll
        for (int i = 0; i < 2; i++) {
            const int task = tid + 256 * i;
            const int r = task >> 2, sg = task & 3;
            const int kw = ks * 16 + 4 * sg;
            size_t aw;
            if (MODE == 0) {
                aw = (size_t)(m0 + r) * 512 + kw;
            } else {
                const int m = m0 + r, b = m >> 11, t = m & 2047;
                aw = (((size_t)b * 16 + (kw >> 5)) * 2048 + t) * 32 + (kw & 31);
            }
            const uint32_t so = 4u * (r * GS + 4 * sg);
            cpa16(sb + so,            Ahi_g + aw);
            cpa16(sb + 4u * AW + so,  Alo_g + aw);
        }
        // B arrays: 256 rows x 4 segs = 1024 uint4 tasks -> 4 per thread
#pragma unroll
        for (int i = 0; i < 4; i++) {
            const int task = tid + 256 * i;
            const int r = task >> 2, sg = task & 3;
            const size_t bw = (size_t)(n0 + r) * 512 + ks * 16 + 4 * sg;
            const uint32_t so = 4u * (r * GS + 4 * sg);
            cpa16(sb + 8u * AW + so,             Bhi_g + bw);
            cpa16(sb + 8u * AW + 4u * BW + so,   Blo_g + bw);
        }
    };

    issue(0, 0);
    CP_COMMIT();

    for (int ks = 0; ks < NKS; ks++) {
        const int st = ks & 1;
        if (ks + 1 < NKS) {
            issue(ks + 1, st ^ 1);
            CP_COMMIT();
            CP_WAIT1();
        } else {
            CP_WAIT0();
        }
        __syncthreads();

        const uint32_t aAhi = sbase + 4u * (st * STW);
        const uint32_t aAlo = aAhi + 4u * AW;
        const uint32_t aBhi = aAhi + 8u * AW;
        const uint32_t aBlo = aBhi + 4u * BW;

#pragma unroll
        for (int kc = 0; kc < 2; kc++) {
            uint32_t afh[4][4], afl[4][4];
#pragma unroll
            for (int mt = 0; mt < 4; mt++) {
                const uint32_t wo = 4u * (offA + (wm * 64 + mt * 16) * GS + 8 * kc);
                ldm_x4(afh[mt], aAhi + wo);
                ldm_x4(afl[mt], aAlo + wo);
            }
#pragma unroll
            for (int np = 0; np < 4; np++) {
                uint32_t bhf[4], blf[4];
                const uint32_t wo = 4u * (offB + (wn * 64 + np * 16) * GS + 8 * kc);
                ldm_x4(bhf, aBhi + wo);
                ldm_x4(blf, aBlo + wo);
#pragma unroll
                for (int mt = 0; mt < 4; mt++) {
                    mma_bf16(acc[mt][2 * np], afh[mt], bhf);
                    mma_bf16(acc[mt][2 * np], afh[mt], blf);
                    mma_bf16(acc[mt][2 * np], afl[mt], bhf);
                    mma_bf16(acc[mt][2 * np + 1], afh[mt], bhf + 2);
                    mma_bf16(acc[mt][2 * np + 1], afh[mt], blf + 2);
                    mma_bf16(acc[mt][2 * np + 1], afl[mt], bhf + 2);
                }
            }
        }
        __syncthreads();
    }

    // Epilogue
    const int section = n0 >> 10;      // uniform per CTA (256 divides 1024)
    uint32_t* hiArr = (section == 0) ? g_Qhi : (section == 1) ? g_Khi : g_Vhi;
    uint32_t* loArr = (section == 0) ? g_Qlo : (section == 1) ? g_Klo : g_Vlo;
    const float qscale = (section == 0) ? 0.125f : 1.0f;
#pragma unroll
    for (int mt = 0; mt < 4; mt++) {
#pragma unroll
        for (int nt = 0; nt < 8; nt++) {
            const int cn = n0 + wn * 64 + nt * 8 + 2 * (lane & 3);
#pragma unroll
            for (int rr = 0; rr < 2; rr++) {
                const int m = m0 + wm * 64 + mt * 16 + (lane >> 2) + 8 * rr;
                const float v0 = acc[mt][nt][2 * rr];
                const float v1 = acc[mt][nt][2 * rr + 1];
                if (MODE == 0) {
                    const int t = m & 2047, b = m >> 11;
                    const int nn = cn & 1023;
                    float2 o;
                    if (section == 2) {
                        o = make_float2(v0, v1);
                    } else {
                        const float2 cs = ((const float2*)rope)[(size_t)t * 512 + (nn >> 1)];
                        o = make_float2(v0 * cs.x - v1 * cs.y, v0 * cs.y + v1 * cs.x);
                    }
                    uint32_t hw, lw;
                    split2(o.x * qscale, o.y * qscale, hw, lw);
                    const size_t widx =
                        ((((size_t)b * 16 + (nn >> 6)) * 2048 + t) * 64 + (nn & 63)) >> 1;
                    hiArr[widx] = hw;
                    loArr[widx] = lw;
                } else {
                    *(float2*)(out + (size_t)m * 1024 + cn) = make_float2(v0, v1);
                }
            }
        }
    }
}

// ---------------------------------------------------------------------------
// Flash attention, split-bf16 mma. BQ=128 (8 warps x m16), BK=64, dk=64.
// Q frags from global (pre-scaled 1/8); K/V staged via uint4 copies;
// V fragments via ldmatrix.trans. Epilogue stores O pre-split for proj.
// grid = (16 qblocks, 32 bh), 256 threads.
// ---------------------------------------------------------------------------
#define FS 36

__global__ __launch_bounds__(256) void flash_mma_kernel()
{
    __shared__ uint32_t Khi[64 * FS], Klo[64 * FS];
    __shared__ uint32_t Vhi[64 * FS], Vlo[64 * FS];

    const int tid = threadIdx.x;
    const int lane = tid & 31;
    const int w = tid >> 5;
    const int qb = blockIdx.x, bh = blockIdx.y;

    const int l8 = lane & 7, g = lane >> 3;
    const int offK = (l8 + ((g >> 1) << 3)) * FS + ((g & 1) << 2);
    const int offV = (l8 + ((g & 1) << 3)) * FS + ((g >> 1) << 2);
    const uint32_t aKhi = smem_addr(Khi), aKlo = smem_addr(Klo);
    const uint32_t aVhi = smem_addr(Vhi), aVlo = smem_addr(Vlo);

    // ---- Q fragments from global ----
    uint32_t qh[4][4], ql[4][4];
    {
        const size_t qbase = ((size_t)bh * 2048 + qb * 128) * 32;
        const int r0 = w * 16 + (lane >> 2);
#pragma unroll
        for (int kc = 0; kc < 4; kc++) {
            const int wrd = 8 * kc + (lane & 3);
            qh[kc][0] = g_Qhi[qbase + (size_t)r0 * 32 + wrd];
            qh[kc][1] = g_Qhi[qbase + (size_t)(r0 + 8) * 32 + wrd];
            qh[kc][2] = g_Qhi[qbase + (size_t)r0 * 32 + wrd + 4];
            qh[kc][3] = g_Qhi[qbase + (size_t)(r0 + 8) * 32 + wrd + 4];
            ql[kc][0] = g_Qlo[qbase + (size_t)r0 * 32 + wrd];
            ql[kc][1] = g_Qlo[qbase + (size_t)(r0 + 8) * 32 + wrd];
            ql[kc][2] = g_Qlo[qbase + (size_t)r0 * 32 + wrd + 4];
            ql[kc][3] = g_Qlo[qbase + (size_t)(r0 + 8) * 32 + wrd + 4];
        }
    }

    float m0_ = -1e30f, m1_ = -1e30f, l0_ = 0.f, l1_ = 0.f;
    float o[8][4];
#pragma unroll
    for (int nt = 0; nt < 8; nt++)
#pragma unroll
        for (int r = 0; r < 4; r++) o[nt][r] = 0.f;

    const int cr = tid >> 2;
    const int cq = tid & 3;

    for (int kt = 0; kt < 32; kt++) {
        __syncthreads();
        {
            const size_t gw = ((size_t)bh * 2048 + kt * 64) * 32 + (size_t)cr * 32 + 8 * cq;
            const int sw = cr * FS + 8 * cq;
            *(uint4*)&Khi[sw]     = *(const uint4*)&g_Khi[gw];
            *(uint4*)&Khi[sw + 4] = *(const uint4*)&g_Khi[gw + 4];
            *(uint4*)&Klo[sw]     = *(const uint4*)&g_Klo[gw];
            *(uint4*)&Klo[sw + 4] = *(const uint4*)&g_Klo[gw + 4];
            *(uint4*)&Vhi[sw]     = *(const uint4*)&g_Vhi[gw];
            *(uint4*)&Vhi[sw + 4] = *(const uint4*)&g_Vhi[gw + 4];
            *(uint4*)&Vlo[sw]     = *(const uint4*)&g_Vlo[gw];
            *(uint4*)&Vlo[sw + 4] = *(const uint4*)&g_Vlo[gw + 4];
        }
        __syncthreads();

        // ---- S = (Q/8) @ K^T ----
        float s[8][4];
#pragma unroll
        for (int nt = 0; nt < 8; nt++)
#pragma unroll
            for (int r = 0; r < 4; r++) s[nt][r] = 0.f;
#pragma unroll
        for (int kc = 0; kc < 4; kc++) {
#pragma unroll
            for (int ntp = 0; ntp < 4; ntp++) {
                uint32_t bhf[4], blf[4];
                const uint32_t wo = 4u * (offK + ntp * 16 * FS + 8 * kc);
                ldm_x4(bhf, aKhi + wo);
                ldm_x4(blf, aKlo + wo);
                mma_bf16(s[2 * ntp], qh[kc], bhf);
                mma_bf16(s[2 * ntp], qh[kc], blf);
                mma_bf16(s[2 * ntp], ql[kc], bhf);
                mma_bf16(s[2 * ntp + 1], qh[kc], bhf + 2);
                mma_bf16(s[2 * ntp + 1], qh[kc], blf + 2);
                mma_bf16(s[2 * ntp + 1], ql[kc], bhf + 2);
            }
        }

        // ---- online softmax ----
        float ml0 = -1e30f, ml1 = -1e30f;
#pragma unroll
        for (int nt = 0; nt < 8; nt++) {
            ml0 = fmaxf(ml0, fmaxf(s[nt][0], s[nt][1]));
            ml1 = fmaxf(ml1, fmaxf(s[nt][2], s[nt][3]));
        }
#pragma unroll
        for (int off = 1; off <= 2; off <<= 1) {
            ml0 = fmaxf(ml0, __shfl_xor_sync(0xffffffffu, ml0, off));
            ml1 = fmaxf(ml1, __shfl_xor_sync(0xffffffffu, ml1, off));
        }
        const float mn0 = fmaxf(m0_, ml0), mn1 = fmaxf(m1_, ml1);
        const float a0 = __expf(m0_ - mn0), a1 = __expf(m1_ - mn1);
        m0_ = mn0; m1_ = mn1;
        float rs0 = 0.f, rs1 = 0.f;
#pragma unroll
        for (int nt = 0; nt < 8; nt++) {
            s[nt][0] = __expf(s[nt][0] - mn0);
            s[nt][1] = __expf(s[nt][1] - mn0);
            s[nt][2] = __expf(s[nt][2] - mn1);
            s[nt][3] = __expf(s[nt][3] - mn1);
            rs0 += s[nt][0] + s[nt][1];
            rs1 += s[nt][2] + s[nt][3];
        }
#pragma unroll
        for (int off = 1; off <= 2; off <<= 1) {
            rs0 += __shfl_xor_sync(0xffffffffu, rs0, off);
            rs1 += __shfl_xor_sync(0xffffffffu, rs1, off);
        }
        l0_ = l0_ * a0 + rs0;
        l1_ = l1_ * a1 + rs1;
#pragma unroll
        for (int nt = 0; nt < 8; nt++) {
            o[nt][0] *= a0; o[nt][1] *= a0;
            o[nt][2] *= a1; o[nt][3] *= a1;
        }

        // ---- P fragments (in-register) ----
        uint32_t ph[4][4], pl[4][4];
#pragma unroll
        for (int kc = 0; kc < 4; kc++) {
            split2(s[2 * kc][0], s[2 * kc][1], ph[kc][0], pl[kc][0]);
            split2(s[2 * kc][2], s[2 * kc][3], ph[kc][1], pl[kc][1]);
            split2(s[2 * kc + 1][0], s[2 * kc + 1][1], ph[kc][2], pl[kc][2]);
            split2(s[2 * kc + 1][2], s[2 * kc + 1][3], ph[kc][3], pl[kc][3]);
        }

        // ---- O += P @ V ----
#pragma unroll
        for (int kc = 0; kc < 4; kc++) {
#pragma unroll
            for (int ntp = 0; ntp < 4; ntp++) {
                uint32_t vhf[4], vlf[4];
                const uint32_t wo = 4u * (offV + kc * 16 * FS + ntp * 8);
                ldm_x4t(vhf, aVhi + wo);
                ldm_x4t(vlf, aVlo + wo);
                mma_bf16(o[2 * ntp], ph[kc], vhf);
                mma_bf16(o[2 * ntp], ph[kc], vlf);
                mma_bf16(o[2 * ntp], pl[kc], vhf);
                mma_bf16(o[2 * ntp + 1], ph[kc], vhf + 2);
                mma_bf16(o[2 * ntp + 1], ph[kc], vlf + 2);
                mma_bf16(o[2 * ntp + 1], pl[kc], vhf + 2);
            }
        }
    }

    // ---- normalize + store pre-split O (head-major words) ----
    const float inv0 = 1.f / l0_, inv1 = 1.f / l1_;
    const int qrow = qb * 128 + w * 16 + (lane >> 2);
    const size_t ob = ((size_t)bh * 2048 + qrow) * 32;
#pragma unroll
    for (int nt = 0; nt < 8; nt++) {
        const int wd = nt * 4 + (lane & 3);
        uint32_t hw, lw;
        split2(o[nt][0] * inv0, o[nt][1] * inv0, hw, lw);
        g_Ohi[ob + wd] = hw;
        g_Olo[ob + wd] = lw;
        split2(o[nt][2] * inv1, o[nt][3] * inv1, hw, lw);
        g_Ohi[ob + 8 * 32 + wd] = hw;
        g_Olo[ob + 8 * 32 + wd] = lw;
    }
}

// ---------------------------------------------------------------------------
extern "C" void kernel_launch(void* const* d_in, const int* in_sizes, int n_in,
                              void* d_out, int out_size)
{
    const float* x      = (const float*)d_in[0];   // (2, 2048, 1024)
    const float* rope   = (const float*)d_in[1];   // (2048, 512, 2)
    const float* w_qkv  = (const float*)d_in[2];   // (3072, 1024)
    const float* w_proj = (const float*)d_in[3];   // (1024, 1024)
    float* out = (float*)d_out;                    // (2, 2048, 1024)

    uint4 *xhi, *xlo, *wqhi, *wqlo, *wphi, *wplo;
    cudaGetSymbolAddress((void**)&xhi, g_Xhi);
    cudaGetSymbolAddress((void**)&xlo, g_Xlo);
    cudaGetSymbolAddress((void**)&wqhi, g_WQhi);
    cudaGetSymbolAddress((void**)&wqlo, g_WQlo);
    cudaGetSymbolAddress((void**)&wphi, g_WPhi);
    cudaGetSymbolAddress((void**)&wplo, g_WPlo);
    uint32_t *ohi, *olo;
    cudaGetSymbolAddress((void**)&ohi, g_Ohi);
    cudaGetSymbolAddress((void**)&olo, g_Olo);

    cudaFuncSetAttribute(mma_gemm_kernel<0>,
                         cudaFuncAttributeMaxDynamicSharedMemorySize, GEMM_SMEM);
    cudaFuncSetAttribute(mma_gemm_kernel<1>,
                         cudaFuncAttributeMaxDynamicSharedMemorySize, GEMM_SMEM);

    presplit_kernel<<<2048, 256>>>((const float4*)x, xhi, xlo);
    presplit_kernel<<<1536, 256>>>((const float4*)w_qkv, wqhi, wqlo);
    presplit_kernel<<<512, 256>>>((const float4*)w_proj, wphi, wplo);

    mma_gemm_kernel<0><<<dim3(12, 32), 256, GEMM_SMEM>>>(
        (const uint32_t*)xhi, (const uint32_t*)xlo,
        (const uint32_t*)wqhi, (const uint32_t*)wqlo, rope, nullptr);
    flash_mma_kernel<<<dim3(16, 32), 256>>>();
    mma_gemm_kernel<1><<<dim3(4, 32), 256, GEMM_SMEM>>>(
        ohi, olo, (const uint32_t*)wphi, (const uint32_t*)wplo, nullptr, out);
}

// round 17
// speedup vs baseline: 1.1175x; 1.0326x over previous
#include <cuda_runtime.h>
#include <cuda_bf16.h>
#include <cstdint>

// Problem constants: B=2, T=2048, D=1024, H=16, dk=64
// Pre-split hi/lo bf16-pair word arrays (1 word = 2 bf16 = one fp32 lane pair)
__device__ uint32_t g_Xhi[2097152],  g_Xlo[2097152];    // x       (B,T,D)
__device__ uint32_t g_WQhi[1572864], g_WQlo[1572864];   // w_qkv   (3D,D)
__device__ uint32_t g_WPhi[524288],  g_WPlo[524288];    // w_proj  (D,D)
__device__ uint32_t g_Qhi[2097152],  g_Qlo[2097152];    // head-major (B,H,T,dk)
__device__ uint32_t g_Khi[2097152],  g_Klo[2097152];
__device__ uint32_t g_Vhi[2097152],  g_Vlo[2097152];
__device__ uint32_t g_Ohi[2097152],  g_Olo[2097152];

// ---------------------------------------------------------------------------
// Helpers
// ---------------------------------------------------------------------------
__device__ __forceinline__ void split2(float f0, float f1, uint32_t& hi, uint32_t& lo) {
    __nv_bfloat162 h = __floats2bfloat162_rn(f0, f1);
    float r0 = f0 - __bfloat162float(h.x);
    float r1 = f1 - __bfloat162float(h.y);
    __nv_bfloat162 l = __floats2bfloat162_rn(r0, r1);
    hi = *(uint32_t*)&h;
    lo = *(uint32_t*)&l;
}
__device__ __forceinline__ void mma_bf16(float* d, const uint32_t* a, const uint32_t* b) {
    asm volatile(
        "mma.sync.aligned.m16n8k16.row.col.f32.bf16.bf16.f32 "
        "{%0,%1,%2,%3}, {%4,%5,%6,%7}, {%8,%9}, {%0,%1,%2,%3};"
        : "+f"(d[0]), "+f"(d[1]), "+f"(d[2]), "+f"(d[3])
        : "r"(a[0]), "r"(a[1]), "r"(a[2]), "r"(a[3]), "r"(b[0]), "r"(b[1]));
}
__device__ __forceinline__ void ldm_x4(uint32_t* r, uint32_t addr) {
    asm volatile("ldmatrix.sync.aligned.m8n8.x4.shared.b16 {%0,%1,%2,%3}, [%4];"
                 : "=r"(r[0]), "=r"(r[1]), "=r"(r[2]), "=r"(r[3]) : "r"(addr));
}
__device__ __forceinline__ void ldm_x4t(uint32_t* r, uint32_t addr) {
    asm volatile("ldmatrix.sync.aligned.m8n8.x4.trans.shared.b16 {%0,%1,%2,%3}, [%4];"
                 : "=r"(r[0]), "=r"(r[1]), "=r"(r[2]), "=r"(r[3]) : "r"(addr));
}
__device__ __forceinline__ uint32_t smem_addr(const void* p) {
    return (uint32_t)__cvta_generic_to_shared(p);
}
__device__ __forceinline__ void cpa16(uint32_t saddr, const void* g) {
    asm volatile("cp.async.cg.shared.global [%0], [%1], 16;" :: "r"(saddr), "l"(g));
}
#define CP_COMMIT() asm volatile("cp.async.commit_group;" ::: "memory")
#define CP_WAIT0()  asm volatile("cp.async.wait_group 0;" ::: "memory")
#define CP_WAIT1()  asm volatile("cp.async.wait_group 1;" ::: "memory")

// ---------------------------------------------------------------------------
// Pre-split: fp32 -> hi/lo bf16-pair words. Each thread handles 8 floats.
// ---------------------------------------------------------------------------
__global__ __launch_bounds__(256) void presplit_kernel(
    const float4* __restrict__ src, uint4* __restrict__ hi, uint4* __restrict__ lo)
{
    const int i = blockIdx.x * 256 + threadIdx.x;
    const float4 a = src[2 * i], b = src[2 * i + 1];
    uint4 h, l;
    split2(a.x, a.y, h.x, l.x);
    split2(a.z, a.w, h.y, l.y);
    split2(b.x, b.y, h.z, l.z);
    split2(b.z, b.w, h.w, l.w);
    hi[i] = h;
    lo[i] = l;
}

// ---------------------------------------------------------------------------
// GEMM: out[m,n] = sum_k A[m,k]*W[n,k], split-bf16 (3 mma terms).
// CTA tile 128x128, 128 threads / 4 warps (2m x 2n), WARP TILE 64x64.
// TWO CTAs PER SM (launch_bounds(128,2)): one CTA's MMAs cover the other's
// cp.async waits + barriers. K staged in 32 chunks of 32 floats (16 words),
// cp.async double-buffered, stride 20 words (ldmatrix conflict-free AND
// 16B-aligned rows: 80 bytes/row, so every uint4 cp.async target is aligned).
// MODE 0: A = pre-split x; epilogue RoPE + split-bf16 Q/K/V store (Q * 1/8).
// MODE 1: A = pre-split O (head-major); epilogue fp32 store to out.
// ---------------------------------------------------------------------------
#define GS 20
#define ARRW (128 * GS)               // words per array (2560)
#define STW (4 * ARRW)                // words per stage: Ahi,Alo,Bhi,Blo (10240)
#define GEMM_SMEM (2 * STW * 4)       // 81920 B per CTA (x2 CTAs = 160KB/SM)
#define NKS 32                        // 32 x 32 floats = K=1024

template <int MODE>
__global__ __launch_bounds__(128, 2) void mma_gemm_kernel(
    const uint32_t* __restrict__ Ahi_g, const uint32_t* __restrict__ Alo_g,
    const uint32_t* __restrict__ Bhi_g, const uint32_t* __restrict__ Blo_g,
    const float* __restrict__ rope, float* __restrict__ out)
{
    extern __shared__ uint32_t sm[];
    const uint32_t sbase = smem_addr(sm);

    const int tid = threadIdx.x;
    const int lane = tid & 31;
    const int wid = tid >> 5;       // 0..3
    const int wm = wid & 1;         // m offset 64*wm
    const int wn = wid >> 1;        // n offset 64*wn
    const int m0 = blockIdx.y * 128;
    const int n0 = blockIdx.x * 128;

    float acc[4][8][4];
#pragma unroll
    for (int mt = 0; mt < 4; mt++)
#pragma unroll
        for (int nt = 0; nt < 8; nt++)
#pragma unroll
            for (int r = 0; r < 4; r++) acc[mt][nt][r] = 0.f;

    const int l8 = lane & 7, g = lane >> 3;
    const int offA = (l8 + ((g & 1) << 3)) * GS + ((g & 2) ? 4 : 0);
    const int offB = (l8 + ((g >> 1) << 3)) * GS + ((g & 1) << 2);

    auto issue = [&](int ks, int st) {
        const uint32_t sb = sbase + 4u * (st * STW);
        // A: 128 rows x 4 segs = 512 tasks / 128 thr = 4 per thread
#pragma unroll
        for (int i = 0; i < 4; i++) {
            const int task = tid + 128 * i;
            const int r = task >> 2, sg = task & 3;
            const int kw = ks * 16 + 4 * sg;
            size_t aw;
            if (MODE == 0) {
                aw = (size_t)(m0 + r) * 512 + kw;
            } else {
                const int m = m0 + r, b = m >> 11, t = m & 2047;
                aw = (((size_t)b * 16 + (kw >> 5)) * 2048 + t) * 32 + (kw & 31);
            }
            const uint32_t so = 4u * (r * GS + 4 * sg);
            cpa16(sb + so,             Ahi_g + aw);
            cpa16(sb + 4u * ARRW + so, Alo_g + aw);
        }
        // B: 128 rows x 4 segs = 512 tasks / 128 thr = 4 per thread
#pragma unroll
        for (int i = 0; i < 4; i++) {
            const int task = tid + 128 * i;
            const int r = task >> 2, sg = task & 3;
            const size_t bw = (size_t)(n0 + r) * 512 + ks * 16 + 4 * sg;
            const uint32_t so = 4u * (r * GS + 4 * sg);
            cpa16(sb + 8u * ARRW + so,  Bhi_g + bw);
            cpa16(sb + 12u * ARRW + so, Blo_g + bw);
        }
    };

    issue(0, 0);
    CP_COMMIT();

    for (int ks = 0; ks < NKS; ks++) {
        const int st = ks & 1;
        if (ks + 1 < NKS) {
            issue(ks + 1, st ^ 1);
            CP_COMMIT();
            CP_WAIT1();
        } else {
            CP_WAIT0();
        }
        __syncthreads();

        const uint32_t aAhi = sbase + 4u * (st * STW);
        const uint32_t aAlo = aAhi + 4u * ARRW;
        const uint32_t aBhi = aAhi + 8u * ARRW;
        const uint32_t aBlo = aAhi + 12u * ARRW;

#pragma unroll
        for (int kc = 0; kc < 2; kc++) {
            uint32_t afh[4][4], afl[4][4];
#pragma unroll
            for (int mt = 0; mt < 4; mt++) {
                const uint32_t wo = 4u * (offA + (wm * 64 + mt * 16) * GS + 8 * kc);
                ldm_x4(afh[mt], aAhi + wo);
                ldm_x4(afl[mt], aAlo + wo);
            }
#pragma unroll
            for (int np = 0; np < 4; np++) {
                uint32_t bhf[4], blf[4];
                const uint32_t wo = 4u * (offB + (wn * 64 + np * 16) * GS + 8 * kc);
                ldm_x4(bhf, aBhi + wo);
                ldm_x4(blf, aBlo + wo);
#pragma unroll
                for (int mt = 0; mt < 4; mt++) {
                    mma_bf16(acc[mt][2 * np], afh[mt], bhf);
                    mma_bf16(acc[mt][2 * np], afh[mt], blf);
                    mma_bf16(acc[mt][2 * np], afl[mt], bhf);
                    mma_bf16(acc[mt][2 * np + 1], afh[mt], bhf + 2);
                    mma_bf16(acc[mt][2 * np + 1], afh[mt], blf + 2);
                    mma_bf16(acc[mt][2 * np + 1], afl[mt], bhf + 2);
                }
            }
        }
        __syncthreads();
    }

    // Epilogue
    const int section = n0 >> 10;      // uniform per CTA (128 divides 1024)
    uint32_t* hiArr = (section == 0) ? g_Qhi : (section == 1) ? g_Khi : g_Vhi;
    uint32_t* loArr = (section == 0) ? g_Qlo : (section == 1) ? g_Klo : g_Vlo;
    const float qscale = (section == 0) ? 0.125f : 1.0f;
#pragma unroll
    for (int mt = 0; mt < 4; mt++) {
#pragma unroll
        for (int nt = 0; nt < 8; nt++) {
            const int cn = n0 + wn * 64 + nt * 8 + 2 * (lane & 3);
#pragma unroll
            for (int rr = 0; rr < 2; rr++) {
                const int m = m0 + wm * 64 + mt * 16 + (lane >> 2) + 8 * rr;
                const float v0 = acc[mt][nt][2 * rr];
                const float v1 = acc[mt][nt][2 * rr + 1];
                if (MODE == 0) {
                    const int t = m & 2047, b = m >> 11;
                    const int nn = cn & 1023;
                    float2 o;
                    if (section == 2) {
                        o = make_float2(v0, v1);
                    } else {
                        const float2 cs = ((const float2*)rope)[(size_t)t * 512 + (nn >> 1)];
                        o = make_float2(v0 * cs.x - v1 * cs.y, v0 * cs.y + v1 * cs.x);
                    }
                    uint32_t hw, lw;
                    split2(o.x * qscale, o.y * qscale, hw, lw);
                    const size_t widx =
                        ((((size_t)b * 16 + (nn >> 6)) * 2048 + t) * 64 + (nn & 63)) >> 1;
                    hiArr[widx] = hw;
                    loArr[widx] = lw;
                } else {
                    *(float2*)(out + (size_t)m * 1024 + cn) = make_float2(v0, v1);
                }
            }
        }
    }
}

// ---------------------------------------------------------------------------
// Flash attention, split-bf16 mma. BQ=128 (8 warps x m16), BK=64, dk=64.
// Q frags from global (pre-scaled 1/8); K/V staged via uint4 copies;
// V fragments via ldmatrix.trans. Epilogue stores O pre-split for proj.
// grid = (16 qblocks, 32 bh), 256 threads.
// ---------------------------------------------------------------------------
#define FS 36

__global__ __launch_bounds__(256) void flash_mma_kernel()
{
    __shared__ uint32_t Khi[64 * FS], Klo[64 * FS];
    __shared__ uint32_t Vhi[64 * FS], Vlo[64 * FS];

    const int tid = threadIdx.x;
    const int lane = tid & 31;
    const int w = tid >> 5;
    const int qb = blockIdx.x, bh = blockIdx.y;

    const int l8 = lane & 7, g = lane >> 3;
    const int offK = (l8 + ((g >> 1) << 3)) * FS + ((g & 1) << 2);
    const int offV = (l8 + ((g & 1) << 3)) * FS + ((g >> 1) << 2);
    const uint32_t aKhi = smem_addr(Khi), aKlo = smem_addr(Klo);
    const uint32_t aVhi = smem_addr(Vhi), aVlo = smem_addr(Vlo);

    // ---- Q fragments from global ----
    uint32_t qh[4][4], ql[4][4];
    {
        const size_t qbase = ((size_t)bh * 2048 + qb * 128) * 32;
        const int r0 = w * 16 + (lane >> 2);
#pragma unroll
        for (int kc = 0; kc < 4; kc++) {
            const int wrd = 8 * kc + (lane & 3);
            qh[kc][0] = g_Qhi[qbase + (size_t)r0 * 32 + wrd];
            qh[kc][1] = g_Qhi[qbase + (size_t)(r0 + 8) * 32 + wrd];
            qh[kc][2] = g_Qhi[qbase + (size_t)r0 * 32 + wrd + 4];
            qh[kc][3] = g_Qhi[qbase + (size_t)(r0 + 8) * 32 + wrd + 4];
            ql[kc][0] = g_Qlo[qbase + (size_t)r0 * 32 + wrd];
            ql[kc][1] = g_Qlo[qbase + (size_t)(r0 + 8) * 32 + wrd];
            ql[kc][2] = g_Qlo[qbase + (size_t)r0 * 32 + wrd + 4];
            ql[kc][3] = g_Qlo[qbase + (size_t)(r0 + 8) * 32 + wrd + 4];
        }
    }

    float m0_ = -1e30f, m1_ = -1e30f, l0_ = 0.f, l1_ = 0.f;
    float o[8][4];
#pragma unroll
    for (int nt = 0; nt < 8; nt++)
#pragma unroll
        for (int r = 0; r < 4; r++) o[nt][r] = 0.f;

    const int cr = tid >> 2;
    const int cq = tid & 3;

    for (int kt = 0; kt < 32; kt++) {
        __syncthreads();
        {
            const size_t gw = ((size_t)bh * 2048 + kt * 64) * 32 + (size_t)cr * 32 + 8 * cq;
            const int sw = cr * FS + 8 * cq;
            *(uint4*)&Khi[sw]     = *(const uint4*)&g_Khi[gw];
            *(uint4*)&Khi[sw + 4] = *(const uint4*)&g_Khi[gw + 4];
            *(uint4*)&Klo[sw]     = *(const uint4*)&g_Klo[gw];
            *(uint4*)&Klo[sw + 4] = *(const uint4*)&g_Klo[gw + 4];
            *(uint4*)&Vhi[sw]     = *(const uint4*)&g_Vhi[gw];
            *(uint4*)&Vhi[sw + 4] = *(const uint4*)&g_Vhi[gw + 4];
            *(uint4*)&Vlo[sw]     = *(const uint4*)&g_Vlo[gw];
            *(uint4*)&Vlo[sw + 4] = *(const uint4*)&g_Vlo[gw + 4];
        }
        __syncthreads();

        // ---- S = (Q/8) @ K^T ----
        float s[8][4];
#pragma unroll
        for (int nt = 0; nt < 8; nt++)
#pragma unroll
            for (int r = 0; r < 4; r++) s[nt][r] = 0.f;
#pragma unroll
        for (int kc = 0; kc < 4; kc++) {
#pragma unroll
            for (int ntp = 0; ntp < 4; ntp++) {
                uint32_t bhf[4], blf[4];
                const uint32_t wo = 4u * (offK + ntp * 16 * FS + 8 * kc);
                ldm_x4(bhf, aKhi + wo);
                ldm_x4(blf, aKlo + wo);
                mma_bf16(s[2 * ntp], qh[kc], bhf);
                mma_bf16(s[2 * ntp], qh[kc], blf);
                mma_bf16(s[2 * ntp], ql[kc], bhf);
                mma_bf16(s[2 * ntp + 1], qh[kc], bhf + 2);
                mma_bf16(s[2 * ntp + 1], qh[kc], blf + 2);
                mma_bf16(s[2 * ntp + 1], ql[kc], bhf + 2);
            }
        }

        // ---- online softmax ----
        float ml0 = -1e30f, ml1 = -1e30f;
#pragma unroll
        for (int nt = 0; nt < 8; nt++) {
            ml0 = fmaxf(ml0, fmaxf(s[nt][0], s[nt][1]));
            ml1 = fmaxf(ml1, fmaxf(s[nt][2], s[nt][3]));
        }
#pragma unroll
        for (int off = 1; off <= 2; off <<= 1) {
            ml0 = fmaxf(ml0, __shfl_xor_sync(0xffffffffu, ml0, off));
            ml1 = fmaxf(ml1, __shfl_xor_sync(0xffffffffu, ml1, off));
        }
        const float mn0 = fmaxf(m0_, ml0), mn1 = fmaxf(m1_, ml1);
        const float a0 = __expf(m0_ - mn0), a1 = __expf(m1_ - mn1);
        m0_ = mn0; m1_ = mn1;
        float rs0 = 0.f, rs1 = 0.f;
#pragma unroll
        for (int nt = 0; nt < 8; nt++) {
            s[nt][0] = __expf(s[nt][0] - mn0);
            s[nt][1] = __expf(s[nt][1] - mn0);
            s[nt][2] = __expf(s[nt][2] - mn1);
            s[nt][3] = __expf(s[nt][3] - mn1);
            rs0 += s[nt][0] + s[nt][1];
            rs1 += s[nt][2] + s[nt][3];
        }
#pragma unroll
        for (int off = 1; off <= 2; off <<= 1) {
            rs0 += __shfl_xor_sync(0xffffffffu, rs0, off);
            rs1 += __shfl_xor_sync(0xffffffffu, rs1, off);
        }
        l0_ = l0_ * a0 + rs0;
        l1_ = l1_ * a1 + rs1;
#pragma unroll
        for (int nt = 0; nt < 8; nt++) {
            o[nt][0] *= a0; o[nt][1] *= a0;
            o[nt][2] *= a1; o[nt][3] *= a1;
        }

        // ---- P fragments (in-register) ----
        uint32_t ph[4][4], pl[4][4];
#pragma unroll
        for (int kc = 0; kc < 4; kc++) {
            split2(s[2 * kc][0], s[2 * kc][1], ph[kc][0], pl[kc][0]);
            split2(s[2 * kc][2], s[2 * kc][3], ph[kc][1], pl[kc][1]);
            split2(s[2 * kc + 1][0], s[2 * kc + 1][1], ph[kc][2], pl[kc][2]);
            split2(s[2 * kc + 1][2], s[2 * kc + 1][3], ph[kc][3], pl[kc][3]);
        }

        // ---- O += P @ V ----
#pragma unroll
        for (int kc = 0; kc < 4; kc++) {
#pragma unroll
            for (int ntp = 0; ntp < 4; ntp++) {
                uint32_t vhf[4], vlf[4];
                const uint32_t wo = 4u * (offV + kc * 16 * FS + ntp * 8);
                ldm_x4t(vhf, aVhi + wo);
                ldm_x4t(vlf, aVlo + wo);
                mma_bf16(o[2 * ntp], ph[kc], vhf);
                mma_bf16(o[2 * ntp], ph[kc], vlf);
                mma_bf16(o[2 * ntp], pl[kc], vhf);
                mma_bf16(o[2 * ntp + 1], ph[kc], vhf + 2);
                mma_bf16(o[2 * ntp + 1], ph[kc], vlf + 2);
                mma_bf16(o[2 * ntp + 1], pl[kc], vhf + 2);
            }
        }
    }

    // ---- normalize + store pre-split O (head-major words) ----
    const float inv0 = 1.f / l0_, inv1 = 1.f / l1_;
    const int qrow = qb * 128 + w * 16 + (lane >> 2);
    const size_t ob = ((size_t)bh * 2048 + qrow) * 32;
#pragma unroll
    for (int nt = 0; nt < 8; nt++) {
        const int wd = nt * 4 + (lane & 3);
        uint32_t hw, lw;
        split2(o[nt][0] * inv0, o[nt][1] * inv0, hw, lw);
        g_Ohi[ob + wd] = hw;
        g_Olo[ob + wd] = lw;
        split2(o[nt][2] * inv1, o[nt][3] * inv1, hw, lw);
        g_Ohi[ob + 8 * 32 + wd] = hw;
        g_Olo[ob + 8 * 32 + wd] = lw;
    }
}

// ---------------------------------------------------------------------------
extern "C" void kernel_launch(void* const* d_in, const int* in_sizes, int n_in,
                              void* d_out, int out_size)
{
    const float* x      = (const float*)d_in[0];   // (2, 2048, 1024)
    const float* rope   = (const float*)d_in[1];   // (2048, 512, 2)
    const float* w_qkv  = (const float*)d_in[2];   // (3072, 1024)
    const float* w_proj = (const float*)d_in[3];   // (1024, 1024)
    float* out = (float*)d_out;                    // (2, 2048, 1024)

    uint4 *xhi, *xlo, *wqhi, *wqlo, *wphi, *wplo;
    cudaGetSymbolAddress((void**)&xhi, g_Xhi);
    cudaGetSymbolAddress((void**)&xlo, g_Xlo);
    cudaGetSymbolAddress((void**)&wqhi, g_WQhi);
    cudaGetSymbolAddress((void**)&wqlo, g_WQlo);
    cudaGetSymbolAddress((void**)&wphi, g_WPhi);
    cudaGetSymbolAddress((void**)&wplo, g_WPlo);
    uint32_t *ohi, *olo;
    cudaGetSymbolAddress((void**)&ohi, g_Ohi);
    cudaGetSymbolAddress((void**)&olo, g_Olo);

    cudaFuncSetAttribute(mma_gemm_kernel<0>,
                         cudaFuncAttributeMaxDynamicSharedMemorySize, GEMM_SMEM);
    cudaFuncSetAttribute(mma_gemm_kernel<1>,
                         cudaFuncAttributeMaxDynamicSharedMemorySize, GEMM_SMEM);

    presplit_kernel<<<2048, 256>>>((const float4*)x, xhi, xlo);
    presplit_kernel<<<1536, 256>>>((const float4*)w_qkv, wqhi, wqlo);
    presplit_kernel<<<512, 256>>>((const float4*)w_proj, wphi, wplo);

    mma_gemm_kernel<0><<<dim3(24, 32), 128, GEMM_SMEM>>>(
        (const uint32_t*)xhi, (const uint32_t*)xlo,
        (const uint32_t*)wqhi, (const uint32_t*)wqlo, rope, nullptr);
    flash_mma_kernel<<<dim3(16, 32), 256>>>();
    mma_gemm_kernel<1><<<dim3(8, 32), 128, GEMM_SMEM>>>(
        ohi, olo, (const uint32_t*)wphi, (const uint32_t*)wplo, nullptr, out);
}